// round 8
// baseline (speedup 1.0000x reference)
#include <cuda_runtime.h>

typedef unsigned long long u64;

#define HALF     512
#define BATCH    8192
#define DEPTH    20
#define TB       8           // batch columns per block (4 warps x 2 cols)
#define NTHREADS 128
#define NBLOCKS  (BATCH / TB)

// Natural-order (cos, sin) table, 8B/pair, 80 KB (L1-resident: smem 4x32KB=128KB -> L1 100KB).
__device__ float2 g_cs[DEPTH * HALF];

__global__ void sincos_kernel(const float* __restrict__ ang) {
    int i = blockIdx.x * blockDim.x + threadIdx.x;
    if (i < DEPTH * HALF) {
        float s, c;
        sincosf(ang[i], &s, &c);
        g_cs[i] = make_float2(c, s);
    }
}

__device__ __forceinline__ float xsign(float v, unsigned m) {
    return __int_as_float(__float_as_int(v) ^ (int)m);
}

// Staging swizzle (float2 units): addr(row, slot) = row*4 + (slot ^ ((row>>2)&3)).
// Optimal 2-phase in both patterns: (a) 8 consecutive rows x 4 slots,
// (b) 32 consecutive rows x 1 slot. Bijective.
__device__ __forceinline__ int sw(int row, int slot) {
    return row * 4 + (slot ^ ((row >> 2) & 3));
}

extern "C" __global__ void __launch_bounds__(NTHREADS, 4)
butterfly_kernel(const float* __restrict__ X, float* __restrict__ Y)
{
    __shared__ float2 tile[1024 * 4];      // 32 KB staging

    const int tid = threadIdx.x;
    const int rt  = tid & 31;              // lane = row-thread (shuffle partner = rt^s)
    const int w   = tid >> 5;              // warp -> columns 2w, 2w+1 of the block's 8
    const long long bbase = (long long)blockIdx.x * TB;

    // Thread-private state, layout B: xr[2j], xr[2j+1] = row rt+32j, cols (2w, 2w+1)
    float xr[64];

    // ---- stage in: gmem (coalesced) -> smem -> registers (layout B) ----
    {
        const int lrow = tid >> 2;         // 0..31
        const int lws  = tid & 3;          // float2 slot (2 cols)
#pragma unroll
        for (int i = 0; i < 32; ++i) {
            const int row = i * 32 + lrow;
            tile[sw(row, lws)] =
                __ldcg(reinterpret_cast<const float2*>(X + (long long)row * BATCH + bbase) + lws);
        }
    }
    __syncthreads();
#pragma unroll
    for (int j = 0; j < 32; ++j) {
        const float2 v = tile[sw(rt + 32 * j, w)];
        xr[2 * j] = v.x; xr[2 * j + 1] = v.y;
    }

#pragma unroll 1
    for (int sp = 0; sp < 2; ++sp) {
        // ---- layers sp*10 + (0..4): strides 1..16 -> warp shuffle, no barriers ----
#pragma unroll
        for (int l = 0; l < 5; ++l) {
            const int s = 1 << l;
            const float2* cp = g_cs + (sp * 10 + l) * HALF;
            const unsigned smask = (rt & s) ? 0x80000000u : 0u;  // upper half: y = c*own - s*other
            const int pb = ((rt >> 1) & ~(s - 1)) + (rt & (s - 1));
#pragma unroll
            for (int j = 0; j < 32; ++j) {
                const float2 cs = __ldg(cp + 16 * j + pb);
                const float sv  = xsign(cs.y, smask);
                const float xoa = __shfl_xor_sync(0xFFFFFFFFu, xr[2 * j], s);
                const float xob = __shfl_xor_sync(0xFFFFFFFFu, xr[2 * j + 1], s);
                xr[2 * j]     = fmaf(cs.x, xr[2 * j],     sv * xoa);
                xr[2 * j + 1] = fmaf(cs.x, xr[2 * j + 1], sv * xob);
            }
        }

        // ---- layers sp*10 + (5..9): strides 32..512 -> in-register pairs (j, j+sg) ----
#pragma unroll
        for (int l = 0; l < 5; ++l) {
            const int sg = 1 << l;
            const float2* cp = g_cs + (sp * 10 + 5 + l) * HALF + rt;
#pragma unroll
            for (int m = 0; m < 16; ++m) {
                const int j = ((m >> l) << (l + 1)) | (m & (sg - 1));
                const int p = (j & ~(2 * sg - 1)) * 16 + (j & (sg - 1)) * 32;
                const float2 cs = __ldg(cp + p);
                const float ns = -cs.y;
                const float x0a = xr[2 * j],            x0b = xr[2 * j + 1];
                const float x1a = xr[2 * (j + sg)],     x1b = xr[2 * (j + sg) + 1];
                xr[2 * j]            = fmaf(cs.x, x0a, cs.y * x1a);
                xr[2 * j + 1]        = fmaf(cs.x, x0b, cs.y * x1b);
                xr[2 * (j + sg)]     = fmaf(cs.x, x1a, ns * x0a);
                xr[2 * (j + sg) + 1] = fmaf(cs.x, x1b, ns * x0b);
            }
        }
    }

    // ---- stage out: registers (layout B) -> smem -> gmem (coalesced) ----
    __syncthreads();                       // all load-phase tile reads finished
#pragma unroll
    for (int j = 0; j < 32; ++j)
        tile[sw(rt + 32 * j, w)] = make_float2(xr[2 * j], xr[2 * j + 1]);
    __syncthreads();
    {
        const int lrow = tid >> 2;
        const int lws  = tid & 3;
#pragma unroll
        for (int i = 0; i < 32; ++i) {
            const int row = i * 32 + lrow;
            const float2 v = tile[sw(row, lws)];
            __stcg(reinterpret_cast<float2*>(Y + (long long)row * BATCH + bbase) + lws, v);
        }
    }
}

extern "C" void kernel_launch(void* const* d_in, const int* in_sizes, int n_in,
                              void* d_out, int out_size)
{
    const float* X = (const float*)d_in[0];
    const float* A = (const float*)d_in[1];
    if (n_in >= 2 && in_sizes[0] < in_sizes[1]) {   // defensive: X is the big one
        const float* t = X; X = A; A = t;
    }
    float* Y = (float*)d_out;

    sincos_kernel<<<(DEPTH * HALF + 255) / 256, 256>>>(A);
    butterfly_kernel<<<NBLOCKS, NTHREADS>>>(X, Y);
}